// round 15
// baseline (speedup 1.0000x reference)
#include <cuda_runtime.h>
#include <cuda_fp16.h>
#include <math.h>
#include <stdint.h>

#define NN    50000
#define FH    128      // H*C
#define NH    4
#define EMAX  800000
#define NEG   0.2f
#define NBMAX 256      // >= ceil(NN/256) scan blocks
#define LOG2E 1.44269504088896f

// ---------------- scratch (static device globals; no runtime alloc) --------
__device__ float  g_xp[NN * FH];         // projected features fp32 [N][128]
__device__ float  g_asrc[NN * NH];       // prescaled by log2e
__device__ float  g_adst[NN * NH];       // prescaled by log2e
__device__ int    g_deg[NN];             // real-edge counts; re-zeroed in scan
__device__ int    g_ord[EMAX];           // per-edge ordinal within its dst row
__device__ int    g_rowptr[NN + 1];
__device__ int    g_bval[NBMAX];
__device__ volatile int g_bflag[NBMAX];
__device__ int    g_hdone;               // hist phase counter; reset by k_agg
__device__ int    g_csr[EMAX + NN];
__device__ float4 g_w4[EMAX + NN];       // per-slot softmax weights (4 heads)

// ---------------- helpers ---------------------------------------------------
__device__ __forceinline__ void mma_f16(float* c, const uint32_t* a,
                                        uint32_t b0, uint32_t b1) {
    asm volatile(
        "mma.sync.aligned.m16n8k16.row.col.f32.f16.f16.f32 "
        "{%0,%1,%2,%3}, {%4,%5,%6,%7}, {%8,%9}, {%0,%1,%2,%3};"
        : "+f"(c[0]), "+f"(c[1]), "+f"(c[2]), "+f"(c[3])
        : "r"(a[0]), "r"(a[1]), "r"(a[2]), "r"(a[3]), "r"(b0), "r"(b1));
}

__device__ __forceinline__ void ffma2(unsigned long long& acc, unsigned long long v,
                                      unsigned long long w2) {
    asm("fma.rn.f32x2 %0, %1, %2, %0;" : "+l"(acc) : "l"(v), "l"(w2));
}

__device__ __forceinline__ float ex2(float a) {
    float r;
    asm("ex2.approx.f32 %0, %1;" : "=f"(r) : "f"(a));
    return r;
}

__device__ __forceinline__ float lrelu(float a) { return fmaxf(a, NEG * a); }

// ---------------- GEMM: xp = x @ W^T via fp16 m16n8k16 tensor cores ---------
#define XPH 24    // smem pitch in halves
__global__ __launch_bounds__(512) void k_gemm(
    const float* __restrict__ x, const float* __restrict__ W,
    const float* __restrict__ attS, const float* __restrict__ attD, int n)
{
    __shared__ __half xsh[128 * XPH];
    __shared__ __half wsh[128 * XPH];
    __shared__ float sAttS[128], sAttD[128];
    __shared__ float sAs[128 * 4], sAd[128 * 4];

    int t = threadIdx.x;
    // prescale by log2e: exp(leaky(z)) == exp2(leaky(z*log2e)) (leaky pos-homog.)
    if (t < 128) { sAttS[t] = attS[t] * LOG2E; sAttD[t] = attD[t] * LOG2E; }

    int row0 = blockIdx.x * 128;
    int wid = t >> 5, lane = t & 31;
    int wm = wid >> 2, wn = wid & 3;      // warp coords: 4 x 4
    int g = lane >> 2, q4 = lane & 3;

    float acc[2][4][4];
#pragma unroll
    for (int mt = 0; mt < 2; mt++)
#pragma unroll
        for (int nt = 0; nt < 4; nt++)
#pragma unroll
            for (int c = 0; c < 4; c++) acc[mt][nt][c] = 0.f;

    for (int kc = 0; kc < 128; kc += 16) {
        {
            int r = t >> 2, q = t & 3;
            float4 v = make_float4(0.f, 0.f, 0.f, 0.f);
            if (row0 + r < n) v = *(const float4*)(x + (size_t)(row0 + r) * 128 + kc + q * 4);
            __half2* p = (__half2*)(xsh + r * XPH + q * 4);
            p[0] = __floats2half2_rn(v.x, v.y);
            p[1] = __floats2half2_rn(v.z, v.w);
        }
        {
            int oc = t >> 2, q = t & 3;
            float4 v = *(const float4*)(W + (size_t)oc * 128 + kc + q * 4);
            __half2* p = (__half2*)(wsh + oc * XPH + q * 4);
            p[0] = __floats2half2_rn(v.x, v.y);
            p[1] = __floats2half2_rn(v.z, v.w);
        }
        __syncthreads();

        uint32_t a[2][4];
#pragma unroll
        for (int mt = 0; mt < 2; mt++) {
            const __half* base = xsh + (wm * 32 + mt * 16 + g) * XPH + 2 * q4;
            a[mt][0] = *(const uint32_t*)(base);
            a[mt][1] = *(const uint32_t*)(base + 8 * XPH);
            a[mt][2] = *(const uint32_t*)(base + 8);
            a[mt][3] = *(const uint32_t*)(base + 8 * XPH + 8);
        }
#pragma unroll
        for (int nt = 0; nt < 4; nt++) {
            const __half* bb = wsh + (wn * 32 + nt * 8 + g) * XPH + 2 * q4;
            uint32_t b0 = *(const uint32_t*)(bb);
            uint32_t b1 = *(const uint32_t*)(bb + 8);
#pragma unroll
            for (int mt = 0; mt < 2; mt++)
                mma_f16(acc[mt][nt], a[mt], b0, b1);
        }
        __syncthreads();
    }

#pragma unroll
    for (int mt = 0; mt < 2; mt++) {
#pragma unroll
        for (int half = 0; half < 2; half++) {
            int rl = wm * 32 + mt * 16 + half * 8 + g;
            int r = row0 + rl;
            float ps = 0.f, pd = 0.f;
#pragma unroll
            for (int nt = 0; nt < 4; nt++) {
                int cbase = wn * 32 + nt * 8 + q4 * 2;
                float v0 = acc[mt][nt][half * 2 + 0];
                float v1 = acc[mt][nt][half * 2 + 1];
                ps += v0 * sAttS[cbase] + v1 * sAttS[cbase + 1];
                pd += v0 * sAttD[cbase] + v1 * sAttD[cbase + 1];
                if (r < n)
                    *(float2*)(g_xp + (size_t)r * 128 + cbase) = make_float2(v0, v1);
            }
            ps += __shfl_xor_sync(0xffffffffu, ps, 1);
            ps += __shfl_xor_sync(0xffffffffu, ps, 2);
            pd += __shfl_xor_sync(0xffffffffu, pd, 1);
            pd += __shfl_xor_sync(0xffffffffu, pd, 2);
            if (q4 == 0) {
                sAs[rl * 4 + wn] = ps;
                sAd[rl * 4 + wn] = pd;
            }
        }
    }
    __syncthreads();
    if (t < 128 && row0 + t < n) {
        *(float4*)(g_asrc + (size_t)(row0 + t) * 4) = *(const float4*)(sAs + t * 4);
        *(float4*)(g_adst + (size_t)(row0 + t) * 4) = *(const float4*)(sAd + t * 4);
    }
}

// ---------------- fused hist + scan -----------------------------------------
__global__ __launch_bounds__(256) void k_hs(
    const int* __restrict__ dst, int n, int E, int nhist, int nscan)
{
    __shared__ int s[256];
    int t = threadIdx.x, b = blockIdx.x;

    if (b < nhist) {
        if (b == 0 && t < NBMAX) g_bflag[t] = 0;
        int e = b * 256 + t;
        if (e < E) {
            int d = __ldcs(dst + e);
            g_ord[e] = atomicAdd(&g_deg[d], 1);
        }
        __syncthreads();
        if (t == 0) { __threadfence(); atomicAdd(&g_hdone, 1); }
        return;
    }

    // scan phase: waits for all hist blocks (strictly lower IDs; thread 0 polls)
    if (t == 0) {
        while (*(volatile int*)&g_hdone < nhist) { }
        __threadfence();
    }
    __syncthreads();

    int sb = b - nhist;
    int i = sb * 256 + t;
    int v = 0;
    if (i < n) { v = g_deg[i] + 1; g_deg[i] = 0; }
    s[t] = v;
    __syncthreads();
#pragma unroll
    for (int off = 1; off < 256; off <<= 1) {
        int u = (t >= off) ? s[t - off] : 0;
        __syncthreads();
        s[t] += u;
        __syncthreads();
    }
    int incl = s[t];
    int agg  = s[255];
    if (t == 255) {
        g_bval[sb] = agg;
        __threadfence();
        g_bflag[sb] = 1;
    }
    int part = 0;
    for (int j = t; j < sb; j += 256) {
        while (g_bflag[j] == 0) { }
        part += *(volatile int*)&g_bval[j];
    }
    __syncthreads();
    s[t] = part;
    __syncthreads();
#pragma unroll
    for (int off = 128; off > 0; off >>= 1) {
        if (t < off) s[t] += s[t + off];
        __syncthreads();
    }
    int excl0 = s[0];
    if (i < n) g_rowptr[i] = excl0 + incl - v;
    if (sb == nscan - 1 && t == 255) g_rowptr[n] = excl0 + agg;
}

// ---------------- scatter + per-edge softmax weights ------------------------
// Runs after gemm join (needs g_asrc/g_adst). Latency-bound kernel with issue
// headroom absorbs the weight math, removing it from the agg critical tail.
__global__ void k_scatw(const int* __restrict__ src, const int* __restrict__ dst,
                        int E, int n) {
    int e = blockIdx.x * blockDim.x + threadIdx.x;
    int total = E + n;
    if (e >= total) return;
    int sidx, didx, p;
    if (e < E) {
        sidx = __ldcs(src + e);
        didx = __ldcs(dst + e);
        p = g_rowptr[didx] + __ldcs(g_ord + e);
    } else {
        sidx = didx = e - E;
        p = g_rowptr[sidx + 1] - 1;          // self loop in last slot
    }
    g_csr[p] = sidx;
    float4 as = *(const float4*)(g_asrc + sidx * 4);
    float4 ad = *(const float4*)(g_adst + didx * 4);
    float4 w;
    w.x = ex2(lrelu(as.x + ad.x));
    w.y = ex2(lrelu(as.y + ad.y));
    w.z = ex2(lrelu(as.z + ad.z));
    w.w = ex2(lrelu(as.w + ad.w));
    g_w4[p] = w;
}

// ---------------- aggregation: one warp per destination node ----------------
// Weights precomputed: per edge only w-load + xp-load + 2 FFMA2 + den.
__global__ __launch_bounds__(256) void k_agg(
    const float* __restrict__ bias, float* __restrict__ out, int n)
{
    // reset phase counter for the next graph replay
    if (blockIdx.x == 0 && threadIdx.x == 0) g_hdone = 0;

    int warp = (blockIdx.x * blockDim.x + threadIdx.x) >> 5;
    int lane = threadIdx.x & 31;
    if (warp >= n) return;
    int nd = warp;
    int h = lane >> 3;

    int begin = g_rowptr[nd], end = g_rowptr[nd + 1];

    unsigned long long acc01 = 0ull, acc23 = 0ull;   // packed f32x2 accumulators
    float den = 0.f;
    const float* xpb = g_xp + lane * 4;
    const float* wf  = (const float*)g_w4 + h;       // weight for this lane's head

    int i = begin;
    // head: align to 16B for the int4 csr loads
    for (; i < end && (i & 3); i++) {
        int s0 = g_csr[i];
        float w0 = wf[i * 4];
        ulonglong2 u0 = *(const ulonglong2*)(xpb + (size_t)s0 * 128);
        unsigned long long ww;
        asm("mov.b64 %0, {%1, %1};" : "=l"(ww) : "f"(w0));
        ffma2(acc01, u0.x, ww); ffma2(acc23, u0.y, ww);
        den += w0;
    }
    for (; i + 4 <= end; i += 4) {
        int4 sv = *(const int4*)(g_csr + i);          // 1x LDG.128 for 4 edges
        float w0 = wf[(i + 0) * 4];
        float w1 = wf[(i + 1) * 4];
        float w2 = wf[(i + 2) * 4];
        float w3 = wf[(i + 3) * 4];
        ulonglong2 u0 = *(const ulonglong2*)(xpb + (size_t)sv.x * 128);
        ulonglong2 u1 = *(const ulonglong2*)(xpb + (size_t)sv.y * 128);
        ulonglong2 u2 = *(const ulonglong2*)(xpb + (size_t)sv.z * 128);
        ulonglong2 u3 = *(const ulonglong2*)(xpb + (size_t)sv.w * 128);
        unsigned long long ww;
        asm("mov.b64 %0, {%1, %1};" : "=l"(ww) : "f"(w0));
        ffma2(acc01, u0.x, ww); ffma2(acc23, u0.y, ww);
        asm("mov.b64 %0, {%1, %1};" : "=l"(ww) : "f"(w1));
        ffma2(acc01, u1.x, ww); ffma2(acc23, u1.y, ww);
        asm("mov.b64 %0, {%1, %1};" : "=l"(ww) : "f"(w2));
        ffma2(acc01, u2.x, ww); ffma2(acc23, u2.y, ww);
        asm("mov.b64 %0, {%1, %1};" : "=l"(ww) : "f"(w3));
        ffma2(acc01, u3.x, ww); ffma2(acc23, u3.y, ww);
        den += (w0 + w1) + (w2 + w3);
    }
    for (; i < end; i++) {
        int s0 = g_csr[i];
        float w0 = wf[i * 4];
        ulonglong2 u0 = *(const ulonglong2*)(xpb + (size_t)s0 * 128);
        unsigned long long ww;
        asm("mov.b64 %0, {%1, %1};" : "=l"(ww) : "f"(w0));
        ffma2(acc01, u0.x, ww); ffma2(acc23, u0.y, ww);
        den += w0;
    }

    float ax, ay, az, aw;
    asm("mov.b64 {%0, %1}, %2;" : "=f"(ax), "=f"(ay) : "l"(acc01));
    asm("mov.b64 {%0, %1}, %2;" : "=f"(az), "=f"(aw) : "l"(acc23));

    float inv = 1.0f / (den + 1e-16f);
    float4 bb = ((const float4*)bias)[lane];
    float4 o;
    o.x = ax * inv + bb.x;
    o.y = ay * inv + bb.y;
    o.z = az * inv + bb.z;
    o.w = aw * inv + bb.w;
    o.x = o.x > 0.f ? o.x : (__expf(o.x) - 1.f);
    o.y = o.y > 0.f ? o.y : (__expf(o.y) - 1.f);
    o.z = o.z > 0.f ? o.z : (__expf(o.z) - 1.f);
    o.w = o.w > 0.f ? o.w : (__expf(o.w) - 1.f);
    ((float4*)out)[(size_t)nd * 32 + lane] = o;
}

// ---------------- launch ----------------------------------------------------
extern "C" void kernel_launch(void* const* d_in, const int* in_sizes, int n_in,
                              void* d_out, int out_size)
{
    const float* x    = (const float*)d_in[0];
    const float* W    = (const float*)d_in[1];
    const float* attS = (const float*)d_in[2];
    const float* attD = (const float*)d_in[3];
    const float* bias = (const float*)d_in[4];
    const int*   ei   = (const int*)d_in[5];

    int n = in_sizes[0] / FH;        // 50000
    int E = in_sizes[5] / 2;         // 800000
    const int* src = ei;
    const int* dst = ei + E;

    int nhist = (E + 255) / 256;                 // 3125
    int nscan = (n + 255) / 256;                 // 196

    // host-side resources, created once (host objects only; no device memory)
    static cudaStream_t s_side = nullptr;
    static cudaEvent_t  ev_fork = nullptr, ev_join = nullptr;
    if (s_side == nullptr) {
        cudaStreamCreateWithFlags(&s_side, cudaStreamNonBlocking);
        cudaEventCreateWithFlags(&ev_fork, cudaEventDisableTiming);
        cudaEventCreateWithFlags(&ev_join, cudaEventDisableTiming);
    }

    // fork: GEMM on side stream; hist+scan on main stream (independent)
    cudaEventRecord(ev_fork, 0);
    cudaStreamWaitEvent(s_side, ev_fork, 0);
    k_gemm<<<(n + 127) / 128, 512, 0, s_side>>>(x, W, attS, attD, n);
    cudaEventRecord(ev_join, s_side);

    k_hs<<<nhist + nscan, 256>>>(dst, n, E, nhist, nscan);

    // scatter+weights needs gemm's asrc/adst -> join here
    cudaStreamWaitEvent(0, ev_join, 0);
    k_scatw<<<(E + n + 255) / 256, 256>>>(src, dst, E, n);
    k_agg<<<(n * 32 + 255) / 256, 256>>>(bias, (float*)d_out, n);
}

// round 16
// speedup vs baseline: 1.0163x; 1.0163x over previous
#include <cuda_runtime.h>
#include <cuda_fp16.h>
#include <math.h>
#include <stdint.h>

#define NN    50000
#define FH    128      // H*C
#define NH    4
#define EMAX  800000
#define NEG   0.2f
#define NBMAX 256      // >= ceil(NN/256) scan blocks
#define LOG2E 1.44269504088896f

// ---------------- scratch (static device globals; no runtime alloc) --------
__device__ __half g_xph[NN * FH];        // projected features fp16 [N][128]
__device__ float  g_asrc[NN * NH];       // prescaled by log2e
__device__ float  g_adst[NN * NH];       // prescaled by log2e
__device__ int    g_deg[NN];             // real-edge counts; re-zeroed in scan
__device__ int    g_ord[EMAX];           // per-edge ordinal within its dst row
__device__ int    g_rowptr[NN + 1];
__device__ int    g_bval[NBMAX];
__device__ volatile int g_bflag[NBMAX];
__device__ int    g_hdone;               // hist phase counter; reset by k_agg
__device__ int    g_csr[EMAX + NN];
__device__ float4 g_w4[EMAX + NN];       // per-slot softmax weights (4 heads)

// ---------------- helpers ---------------------------------------------------
__device__ __forceinline__ void mma_f16(float* c, const uint32_t* a,
                                        uint32_t b0, uint32_t b1) {
    asm volatile(
        "mma.sync.aligned.m16n8k16.row.col.f32.f16.f16.f32 "
        "{%0,%1,%2,%3}, {%4,%5,%6,%7}, {%8,%9}, {%0,%1,%2,%3};"
        : "+f"(c[0]), "+f"(c[1]), "+f"(c[2]), "+f"(c[3])
        : "r"(a[0]), "r"(a[1]), "r"(a[2]), "r"(a[3]), "r"(b0), "r"(b1));
}

__device__ __forceinline__ float ex2(float a) {
    float r;
    asm("ex2.approx.f32 %0, %1;" : "=f"(r) : "f"(a));
    return r;
}

__device__ __forceinline__ float lrelu(float a) { return fmaxf(a, NEG * a); }

// ---------------- k_att: a_src/a_dst directly from x ------------------------
// a_src[n][h] = x[n] . (W^T attS)_h  — project attention vectors once per
// block (cheap, W L2-hot), then one coalesced-ish pass over x. Runs BEFORE
// the big GEMM so k_scatw can start early and overlap it.
__global__ __launch_bounds__(256) void k_att(
    const float* __restrict__ x, const float* __restrict__ W,
    const float* __restrict__ attS, const float* __restrict__ attD, int n)
{
    __shared__ float sv[8][128];   // vec 0-3: S heads, 4-7: D heads
    __shared__ float sa[256];      // attS||attD, prescaled by log2e
    int t = threadIdx.x;
    sa[t] = (t < 128 ? attS[t] : attD[t - 128]) * LOG2E;
    __syncthreads();

    for (int j = t; j < 8 * 128; j += 256) {
        int v = j >> 7, k = j & 127;
        int h = v & 3;
        const float* wp = W + (h * 32) * 128 + k;
        const float* ap = sa + (v >> 2) * 128 + h * 32;
        float s = 0.f;
#pragma unroll
        for (int c = 0; c < 32; c++) s += wp[c * 128] * ap[c];
        sv[v][k] = s;
    }
    __syncthreads();

    int i = blockIdx.x * 256 + t;
    if (i >= n) return;
    const float4* xr = (const float4*)(x + (size_t)i * 128);
    float r[8] = {0.f, 0.f, 0.f, 0.f, 0.f, 0.f, 0.f, 0.f};
#pragma unroll 4
    for (int q = 0; q < 32; q++) {
        float4 v = xr[q];
#pragma unroll
        for (int vv = 0; vv < 8; vv++) {
            float4 s4 = *(const float4*)&sv[vv][q * 4];   // uniform -> broadcast
            r[vv] += v.x * s4.x + v.y * s4.y + v.z * s4.z + v.w * s4.w;
        }
    }
    *(float4*)(g_asrc + i * 4) = make_float4(r[0], r[1], r[2], r[3]);
    *(float4*)(g_adst + i * 4) = make_float4(r[4], r[5], r[6], r[7]);
}

// ---------------- GEMM: xp = x @ W^T via fp16 m16n8k16, fp16 output ---------
#define XPH 24    // smem pitch in halves
__global__ __launch_bounds__(512) void k_gemm(
    const float* __restrict__ x, const float* __restrict__ W, int n)
{
    __shared__ __half xsh[128 * XPH];
    __shared__ __half wsh[128 * XPH];

    int t = threadIdx.x;
    int row0 = blockIdx.x * 128;
    int wid = t >> 5, lane = t & 31;
    int wm = wid >> 2, wn = wid & 3;      // warp coords: 4 x 4
    int g = lane >> 2, q4 = lane & 3;

    float acc[2][4][4];
#pragma unroll
    for (int mt = 0; mt < 2; mt++)
#pragma unroll
        for (int nt = 0; nt < 4; nt++)
#pragma unroll
            for (int c = 0; c < 4; c++) acc[mt][nt][c] = 0.f;

    for (int kc = 0; kc < 128; kc += 16) {
        {
            int r = t >> 2, q = t & 3;
            float4 v = make_float4(0.f, 0.f, 0.f, 0.f);
            if (row0 + r < n) v = *(const float4*)(x + (size_t)(row0 + r) * 128 + kc + q * 4);
            __half2* p = (__half2*)(xsh + r * XPH + q * 4);
            p[0] = __floats2half2_rn(v.x, v.y);
            p[1] = __floats2half2_rn(v.z, v.w);
        }
        {
            int oc = t >> 2, q = t & 3;
            float4 v = *(const float4*)(W + (size_t)oc * 128 + kc + q * 4);
            __half2* p = (__half2*)(wsh + oc * XPH + q * 4);
            p[0] = __floats2half2_rn(v.x, v.y);
            p[1] = __floats2half2_rn(v.z, v.w);
        }
        __syncthreads();

        uint32_t a[2][4];
#pragma unroll
        for (int mt = 0; mt < 2; mt++) {
            const __half* base = xsh + (wm * 32 + mt * 16 + g) * XPH + 2 * q4;
            a[mt][0] = *(const uint32_t*)(base);
            a[mt][1] = *(const uint32_t*)(base + 8 * XPH);
            a[mt][2] = *(const uint32_t*)(base + 8);
            a[mt][3] = *(const uint32_t*)(base + 8 * XPH + 8);
        }
#pragma unroll
        for (int nt = 0; nt < 4; nt++) {
            const __half* bb = wsh + (wn * 32 + nt * 8 + g) * XPH + 2 * q4;
            uint32_t b0 = *(const uint32_t*)(bb);
            uint32_t b1 = *(const uint32_t*)(bb + 8);
#pragma unroll
            for (int mt = 0; mt < 2; mt++)
                mma_f16(acc[mt][nt], a[mt], b0, b1);
        }
        __syncthreads();
    }

    // epilogue: fp16 xp stores only (attention dots handled by k_att)
#pragma unroll
    for (int mt = 0; mt < 2; mt++) {
#pragma unroll
        for (int half = 0; half < 2; half++) {
            int r = row0 + wm * 32 + mt * 16 + half * 8 + g;
            if (r < n) {
#pragma unroll
                for (int nt = 0; nt < 4; nt++) {
                    int cbase = wn * 32 + nt * 8 + q4 * 2;
                    *(__half2*)(g_xph + (size_t)r * 128 + cbase) =
                        __floats2half2_rn(acc[mt][nt][half * 2 + 0],
                                          acc[mt][nt][half * 2 + 1]);
                }
            }
        }
    }
}

// ---------------- fused hist + scan -----------------------------------------
__global__ __launch_bounds__(256) void k_hs(
    const int* __restrict__ dst, int n, int E, int nhist, int nscan)
{
    __shared__ int s[256];
    int t = threadIdx.x, b = blockIdx.x;

    if (b < nhist) {
        if (b == 0 && t < NBMAX) g_bflag[t] = 0;
        int e = b * 256 + t;
        if (e < E) {
            int d = __ldcs(dst + e);
            g_ord[e] = atomicAdd(&g_deg[d], 1);
        }
        __syncthreads();
        if (t == 0) { __threadfence(); atomicAdd(&g_hdone, 1); }
        return;
    }

    if (t == 0) {
        while (*(volatile int*)&g_hdone < nhist) { }
        __threadfence();
    }
    __syncthreads();

    int sb = b - nhist;
    int i = sb * 256 + t;
    int v = 0;
    if (i < n) { v = g_deg[i] + 1; g_deg[i] = 0; }
    s[t] = v;
    __syncthreads();
#pragma unroll
    for (int off = 1; off < 256; off <<= 1) {
        int u = (t >= off) ? s[t - off] : 0;
        __syncthreads();
        s[t] += u;
        __syncthreads();
    }
    int incl = s[t];
    int agg  = s[255];
    if (t == 255) {
        g_bval[sb] = agg;
        __threadfence();
        g_bflag[sb] = 1;
    }
    int part = 0;
    for (int j = t; j < sb; j += 256) {
        while (g_bflag[j] == 0) { }
        part += *(volatile int*)&g_bval[j];
    }
    __syncthreads();
    s[t] = part;
    __syncthreads();
#pragma unroll
    for (int off = 128; off > 0; off >>= 1) {
        if (t < off) s[t] += s[t + off];
        __syncthreads();
    }
    int excl0 = s[0];
    if (i < n) g_rowptr[i] = excl0 + incl - v;
    if (sb == nscan - 1 && t == 255) g_rowptr[n] = excl0 + agg;
}

// ---------------- scatter + per-edge softmax weights ------------------------
// Needs only k_att's asrc/adst + k_hs's rowptr/ord -> overlaps the big GEMM.
__global__ void k_scatw(const int* __restrict__ src, const int* __restrict__ dst,
                        int E, int n) {
    int e = blockIdx.x * blockDim.x + threadIdx.x;
    int total = E + n;
    if (e >= total) return;
    int sidx, didx, p;
    if (e < E) {
        sidx = __ldcs(src + e);
        didx = __ldcs(dst + e);
        p = g_rowptr[didx] + __ldcs(g_ord + e);
    } else {
        sidx = didx = e - E;
        p = g_rowptr[sidx + 1] - 1;          // self loop in last slot
    }
    g_csr[p] = sidx;
    float4 as = *(const float4*)(g_asrc + sidx * 4);
    float4 ad = *(const float4*)(g_adst + didx * 4);
    float4 w;
    w.x = ex2(lrelu(as.x + ad.x));
    w.y = ex2(lrelu(as.y + ad.y));
    w.z = ex2(lrelu(as.z + ad.z));
    w.w = ex2(lrelu(as.w + ad.w));
    g_w4[p] = w;
}

// ---------------- aggregation: one warp per destination node ----------------
// fp16 xp gather (256 B/edge) + precomputed weights.
__global__ __launch_bounds__(256) void k_agg(
    const float* __restrict__ bias, float* __restrict__ out, int n)
{
    if (blockIdx.x == 0 && threadIdx.x == 0) g_hdone = 0;   // reset for replay

    int warp = (blockIdx.x * blockDim.x + threadIdx.x) >> 5;
    int lane = threadIdx.x & 31;
    if (warp >= n) return;
    int nd = warp;
    int h = lane >> 3;

    int begin = g_rowptr[nd], end = g_rowptr[nd + 1];

    float ax = 0.f, ay = 0.f, az = 0.f, aw = 0.f;
    float den = 0.f;
    const __half* xpb = g_xph + lane * 4;
    const float* wf = (const float*)g_w4 + h;

    int i = begin;
    for (; i < end && (i & 3); i++) {
        int s0 = g_csr[i];
        float w0 = wf[i * 4];
        uint2 u0 = *(const uint2*)(xpb + (size_t)s0 * 128);
        float2 pa = __half22float2(*(__half2*)&u0.x);
        float2 pb = __half22float2(*(__half2*)&u0.y);
        ax = fmaf(w0, pa.x, ax); ay = fmaf(w0, pa.y, ay);
        az = fmaf(w0, pb.x, az); aw = fmaf(w0, pb.y, aw);
        den += w0;
    }
    for (; i + 4 <= end; i += 4) {
        int4 sv = *(const int4*)(g_csr + i);
        float w0 = wf[(i + 0) * 4];
        float w1 = wf[(i + 1) * 4];
        float w2 = wf[(i + 2) * 4];
        float w3 = wf[(i + 3) * 4];
        uint2 u0 = *(const uint2*)(xpb + (size_t)sv.x * 128);
        uint2 u1 = *(const uint2*)(xpb + (size_t)sv.y * 128);
        uint2 u2 = *(const uint2*)(xpb + (size_t)sv.z * 128);
        uint2 u3 = *(const uint2*)(xpb + (size_t)sv.w * 128);
        float2 p0a = __half22float2(*(__half2*)&u0.x), p0b = __half22float2(*(__half2*)&u0.y);
        float2 p1a = __half22float2(*(__half2*)&u1.x), p1b = __half22float2(*(__half2*)&u1.y);
        float2 p2a = __half22float2(*(__half2*)&u2.x), p2b = __half22float2(*(__half2*)&u2.y);
        float2 p3a = __half22float2(*(__half2*)&u3.x), p3b = __half22float2(*(__half2*)&u3.y);
        ax = fmaf(w0, p0a.x, fmaf(w1, p1a.x, fmaf(w2, p2a.x, fmaf(w3, p3a.x, ax))));
        ay = fmaf(w0, p0a.y, fmaf(w1, p1a.y, fmaf(w2, p2a.y, fmaf(w3, p3a.y, ay))));
        az = fmaf(w0, p0b.x, fmaf(w1, p1b.x, fmaf(w2, p2b.x, fmaf(w3, p3b.x, az))));
        aw = fmaf(w0, p0b.y, fmaf(w1, p1b.y, fmaf(w2, p2b.y, fmaf(w3, p3b.y, aw))));
        den += (w0 + w1) + (w2 + w3);
    }
    for (; i < end; i++) {
        int s0 = g_csr[i];
        float w0 = wf[i * 4];
        uint2 u0 = *(const uint2*)(xpb + (size_t)s0 * 128);
        float2 pa = __half22float2(*(__half2*)&u0.x);
        float2 pb = __half22float2(*(__half2*)&u0.y);
        ax = fmaf(w0, pa.x, ax); ay = fmaf(w0, pa.y, ay);
        az = fmaf(w0, pb.x, az); aw = fmaf(w0, pb.y, aw);
        den += w0;
    }

    float inv = 1.0f / (den + 1e-16f);
    float4 bb = ((const float4*)bias)[lane];
    float4 o;
    o.x = ax * inv + bb.x;
    o.y = ay * inv + bb.y;
    o.z = az * inv + bb.z;
    o.w = aw * inv + bb.w;
    o.x = o.x > 0.f ? o.x : (__expf(o.x) - 1.f);
    o.y = o.y > 0.f ? o.y : (__expf(o.y) - 1.f);
    o.z = o.z > 0.f ? o.z : (__expf(o.z) - 1.f);
    o.w = o.w > 0.f ? o.w : (__expf(o.w) - 1.f);
    ((float4*)out)[(size_t)nd * 32 + lane] = o;
}

// ---------------- launch ----------------------------------------------------
extern "C" void kernel_launch(void* const* d_in, const int* in_sizes, int n_in,
                              void* d_out, int out_size)
{
    const float* x    = (const float*)d_in[0];
    const float* W    = (const float*)d_in[1];
    const float* attS = (const float*)d_in[2];
    const float* attD = (const float*)d_in[3];
    const float* bias = (const float*)d_in[4];
    const int*   ei   = (const int*)d_in[5];

    int n = in_sizes[0] / FH;        // 50000
    int E = in_sizes[5] / 2;         // 800000
    const int* src = ei;
    const int* dst = ei + E;

    int nhist = (E + 255) / 256;                 // 3125
    int nscan = (n + 255) / 256;                 // 196

    // host-side resources, created once (host objects only; no device memory)
    static cudaStream_t s_side = nullptr;
    static cudaEvent_t  ev_fork = nullptr, ev_att = nullptr, ev_xp = nullptr;
    if (s_side == nullptr) {
        cudaStreamCreateWithFlags(&s_side, cudaStreamNonBlocking);
        cudaEventCreateWithFlags(&ev_fork, cudaEventDisableTiming);
        cudaEventCreateWithFlags(&ev_att, cudaEventDisableTiming);
        cudaEventCreateWithFlags(&ev_xp, cudaEventDisableTiming);
    }

    // side stream: attention halves first (small), then the big projection
    cudaEventRecord(ev_fork, 0);
    cudaStreamWaitEvent(s_side, ev_fork, 0);
    k_att<<<(n + 255) / 256, 256, 0, s_side>>>(x, W, attS, attD, n);
    cudaEventRecord(ev_att, s_side);
    k_gemm<<<(n + 127) / 128, 512, 0, s_side>>>(x, W, n);
    cudaEventRecord(ev_xp, s_side);

    // main stream: hist+scan (independent), then scatter+weights which only
    // needs k_att's outputs -> overlaps the big GEMM
    k_hs<<<nhist + nscan, 256>>>(dst, n, E, nhist, nscan);
    cudaStreamWaitEvent(0, ev_att, 0);
    k_scatw<<<(E + n + 255) / 256, 256>>>(src, dst, E, n);

    // aggregation needs xp -> join on the big GEMM
    cudaStreamWaitEvent(0, ev_xp, 0);
    k_agg<<<(n * 32 + 255) / 256, 256>>>(bias, (float*)d_out, n);
}